// round 16
// baseline (speedup 1.0000x reference)
#include <cuda_runtime.h>
#include <cuda_bf16.h>
#include <math.h>
#include <stdint.h>

// ---------------- problem constants ----------------
constexpr int cB = 16, cL = 256, cS = 100, cLA = 48, cNA = 32, cE = 64;
constexpr int cD = 768, cH = 12, cNHID = 1024, cW = 102, cCAT = 3 * cD; // 2304
#define EPSV 1e-12f
#define RSQRTD 0.03608439182435161f   // 1/sqrt(768)

// ---------------- device scratch ----------------
// cat_e layout: [entity | ahh | toka]  (score-dependent part LAST)
// cat_a layout: [arg | au2u | argtok]
__device__ float g_sent_emb[cB * cS * cD];
__device__ float g_entcat[cB * cE * cCAT];
__device__ float g_nonempty[cB * cE];
__device__ float g_entity2[cB * cE * cD];
__device__ float g_cat_e[cB * cE * cCAT];
__device__ float g_cat_a[cB * cNA * cCAT];
__device__ float g_score[cB * cE * cNA];
__device__ float g_t2t[cB * cS * cS];
__device__ float g_ahh[cB * cS * cD];
__device__ float g_a2a[cB * cNA * cNA];
__device__ float g_Pe[cB * cE * cNHID];
__device__ float g_Pa[cB * cNA * cNHID];
__device__ int   g_idx[cB * cS];
__device__ int   g_nsent[cB];
__device__ int   g_sls[cB];
__device__ int   g_blen[cB];
// bf16 split weight packs (N x K layouts, rows reordered to match cat_e/cat_a)
__device__ __nv_bfloat16 g_WtaT_hi[cD * cCAT];
__device__ __nv_bfloat16 g_WtaT_lo[cD * cCAT];
__device__ __nv_bfloat16 g_W1eT_hi[cNHID * cCAT];
__device__ __nv_bfloat16 g_W1eT_lo[cNHID * cCAT];
__device__ __nv_bfloat16 g_W1aT_hi[cNHID * cCAT];
__device__ __nv_bfloat16 g_W1aT_lo[cNHID * cCAT];

// ================= mma.sync helpers =================
__device__ __forceinline__ uint32_t smem_to_u32(const void* p) {
    uint32_t a;
    asm("{ .reg .u64 t; cvta.to.shared.u64 t, %1; cvt.u32.u64 %0, t; }"
        : "=r"(a) : "l"(p));
    return a;
}
__device__ __forceinline__ void ldsm4(uint32_t (&r)[4], uint32_t addr) {
    asm volatile("ldmatrix.sync.aligned.m8n8.x4.shared.b16 {%0,%1,%2,%3}, [%4];"
        : "=r"(r[0]), "=r"(r[1]), "=r"(r[2]), "=r"(r[3]) : "r"(addr));
}
__device__ __forceinline__ void mma16816(float (&d)[4], const uint32_t (&a)[4],
                                         uint32_t b0, uint32_t b1) {
    asm volatile(
        "mma.sync.aligned.m16n8k16.row.col.f32.bf16.bf16.f32 "
        "{%0,%1,%2,%3}, {%4,%5,%6,%7}, {%8,%9}, {%0,%1,%2,%3};"
        : "+f"(d[0]), "+f"(d[1]), "+f"(d[2]), "+f"(d[3])
        : "r"(a[0]), "r"(a[1]), "r"(a[2]), "r"(a[3]), "r"(b0), "r"(b1));
}

// ================= split-bf16 tensor GEMM: C(MxN) (+)= A(MxK fp32, lda) @ B^T (NxK bf16 hi/lo, ldb)
// block tile 128x128, 8 warps (2m x 4n, warp tile 64x32), K-chunk 32, double buffer.
constexpr int GM_ASTR = 40;                       // bf16 per smem row (pad 32->40)
constexpr int GM_OFF_AH = 0;
constexpr int GM_OFF_AL = 128 * GM_ASTR * 2;      // 10240
constexpr int GM_OFF_BH = 2 * GM_OFF_AL;          // 20480
constexpr int GM_OFF_BL = GM_OFF_BH + 128 * GM_ASTR * 2;   // 30720
constexpr int GM_BUF_BYTES = GM_OFF_BL + 128 * GM_ASTR * 2; // 40960
constexpr int GM_SMEM = 2 * GM_BUF_BYTES;         // 81920

__global__ void __launch_bounds__(256, 1)
mma_gemm_kernel(const float* __restrict__ A,
                const __nv_bfloat16* __restrict__ Bhi,
                const __nv_bfloat16* __restrict__ Blo,
                float* __restrict__ C, int M, int N, int K, int lda, int ldb,
                const float* __restrict__ bias, const float* __restrict__ rowscale,
                int accum) {
    extern __shared__ char smem[];
    uint32_t sbase = smem_to_u32(smem);
    int tid = threadIdx.x, wid = tid >> 5, lane = tid & 31;
    int wm = wid >> 2, wn = wid & 3;
    int bm = blockIdx.y * 128, bn = blockIdx.x * 128;

    float acc[4][4][4];
#pragma unroll
    for (int i = 0; i < 4; i++)
#pragma unroll
        for (int j = 0; j < 4; j++)
#pragma unroll
            for (int q = 0; q < 4; q++) acc[i][j][q] = 0.f;

    int nch = K >> 5;
    float4 aReg[4];
    uint4 bhReg[2], blReg[2];

    auto gload = [&](int c) {
        int k0 = c << 5;
#pragma unroll
        for (int i = 0; i < 4; i++) {
            int idx = tid + i * 256;
            int row = idx >> 3, c4 = idx & 7;
            aReg[i] = *(const float4*)(A + (long)(bm + row) * lda + k0 + c4 * 4);
        }
#pragma unroll
        for (int i = 0; i < 2; i++) {
            int idx = tid + i * 256;
            int row = idx >> 2, c16 = idx & 3;
            long off = (long)(bn + row) * ldb + k0 + c16 * 8;
            bhReg[i] = *(const uint4*)(Bhi + off);
            blReg[i] = *(const uint4*)(Blo + off);
        }
    };
    auto sstore = [&](int buf) {
        char* base = smem + buf * GM_BUF_BYTES;
#pragma unroll
        for (int i = 0; i < 4; i++) {
            int idx = tid + i * 256;
            int row = idx >> 3, c4 = idx & 7;
            float4 v = aReg[i];
            __nv_bfloat162 h01 = __floats2bfloat162_rn(v.x, v.y);
            __nv_bfloat162 h23 = __floats2bfloat162_rn(v.z, v.w);
            __nv_bfloat162 l01 = __floats2bfloat162_rn(v.x - __bfloat162float(h01.x),
                                                       v.y - __bfloat162float(h01.y));
            __nv_bfloat162 l23 = __floats2bfloat162_rn(v.z - __bfloat162float(h23.x),
                                                       v.w - __bfloat162float(h23.y));
            uint2 H, Lo;
            H.x = *(uint32_t*)&h01; H.y = *(uint32_t*)&h23;
            Lo.x = *(uint32_t*)&l01; Lo.y = *(uint32_t*)&l23;
            *(uint2*)(base + GM_OFF_AH + row * (GM_ASTR * 2) + c4 * 8) = H;
            *(uint2*)(base + GM_OFF_AL + row * (GM_ASTR * 2) + c4 * 8) = Lo;
        }
#pragma unroll
        for (int i = 0; i < 2; i++) {
            int idx = tid + i * 256;
            int row = idx >> 2, c16 = idx & 3;
            *(uint4*)(base + GM_OFF_BH + row * (GM_ASTR * 2) + c16 * 16) = bhReg[i];
            *(uint4*)(base + GM_OFF_BL + row * (GM_ASTR * 2) + c16 * 16) = blReg[i];
        }
    };
    auto compute = [&](int buf) {
        uint32_t sb = sbase + buf * GM_BUF_BYTES;
#pragma unroll
        for (int kk = 0; kk < 32; kk += 16) {
            uint32_t ah[4][4], al[4][4];
#pragma unroll
            for (int mf = 0; mf < 4; mf++) {
                uint32_t off = ((wm * 64 + mf * 16 + (lane & 15)) * GM_ASTR +
                                kk + ((lane >> 4) << 3)) * 2;
                ldsm4(ah[mf], sb + GM_OFF_AH + off);
                ldsm4(al[mf], sb + GM_OFF_AL + off);
            }
            uint32_t bh[2][4], bl[2][4];
#pragma unroll
            for (int p = 0; p < 2; p++) {
                int row = wn * 32 + p * 16 + (lane & 7) + ((lane >> 4) << 3);
                int col = kk + (((lane >> 3) & 1) << 3);
                uint32_t off = (row * GM_ASTR + col) * 2;
                ldsm4(bh[p], sb + GM_OFF_BH + off);
                ldsm4(bl[p], sb + GM_OFF_BL + off);
            }
#pragma unroll
            for (int mf = 0; mf < 4; mf++)
#pragma unroll
                for (int nf = 0; nf < 4; nf++) {
                    uint32_t bh0 = bh[nf >> 1][(nf & 1) * 2];
                    uint32_t bh1 = bh[nf >> 1][(nf & 1) * 2 + 1];
                    uint32_t bl0 = bl[nf >> 1][(nf & 1) * 2];
                    uint32_t bl1 = bl[nf >> 1][(nf & 1) * 2 + 1];
                    mma16816(acc[mf][nf], ah[mf], bh0, bh1);
                    mma16816(acc[mf][nf], ah[mf], bl0, bl1);
                    mma16816(acc[mf][nf], al[mf], bh0, bh1);
                }
        }
    };

    gload(0);
    sstore(0);
    __syncthreads();
    for (int c = 0; c < nch; c++) {
        if (c + 1 < nch) gload(c + 1);
        compute(c & 1);
        __syncthreads();
        if (c + 1 < nch) {
            sstore((c + 1) & 1);
            __syncthreads();
        }
    }
    // epilogue
#pragma unroll
    for (int mf = 0; mf < 4; mf++) {
        int m0 = bm + wm * 64 + mf * 16 + (lane >> 2);
        float rs0 = rowscale ? rowscale[m0] : 1.f;
        float rs1 = rowscale ? rowscale[m0 + 8] : 1.f;
#pragma unroll
        for (int nf = 0; nf < 4; nf++) {
            int n = bn + wn * 32 + nf * 8 + (lane & 3) * 2;
            float b0 = 0.f, b1 = 0.f;
            if (bias) { b0 = bias[n]; b1 = bias[n + 1]; }
            float* c0 = C + (long)m0 * N + n;
            float* c1 = C + (long)(m0 + 8) * N + n;
            float2 v0, v1;
            v0.x = (acc[mf][nf][0] + b0) * rs0;
            v0.y = (acc[mf][nf][1] + b1) * rs0;
            v1.x = (acc[mf][nf][2] + b0) * rs1;
            v1.y = (acc[mf][nf][3] + b1) * rs1;
            if (accum) {
                float2 o0 = *(float2*)c0, o1 = *(float2*)c1;
                v0.x += o0.x; v0.y += o0.y;
                v1.x += o1.x; v1.y += o1.y;
            }
            *(float2*)c0 = v0;
            *(float2*)c1 = v1;
        }
    }
}

// ---------------- meta: decode idxs (int32 or int64), per-b scalars ----------------
__global__ void meta_kernel(const void* idxs_raw, const void* blen_raw) {
    const unsigned* u = (const unsigned*)idxs_raw;
    bool is64 = (u[1] == 0u);
    int b = threadIdx.x;
    if (b >= cB) return;
    int nv = 0;
    for (int i = 0; i < cW; i++) {
        long long v = is64 ? ((const long long*)idxs_raw)[b * cW + i]
                           : (long long)((const int*)idxs_raw)[b * cW + i];
        if (v > 0) nv++;
        if (i < cS) g_idx[b * cS + i] = (int)v;
    }
    int sp = nv - 2;
    long long sls = is64 ? ((const long long*)idxs_raw)[b * cW + sp]
                         : (long long)((const int*)idxs_raw)[b * cW + sp];
    g_nsent[b] = sp;
    g_sls[b] = (int)sls;
    long long bl = is64 ? ((const long long*)blen_raw)[b]
                        : (long long)((const int*)blen_raw)[b];
    g_blen[b] = (int)bl;
}

// ---------------- weight transposes + bf16 hi/lo split ----------------
__global__ void tr_wta_kernel(const float* __restrict__ W) {   // (2304x768) -> (768x2304)
    __shared__ float tile[32][33];
    int k0 = blockIdx.x * 32, n0 = blockIdx.y * 32;
    int lane = threadIdx.x & 31, wrow = threadIdx.x >> 5;
    for (int i = wrow; i < 32; i += 8)
        tile[i][lane] = W[(long)(k0 + i) * cD + n0 + lane];
    __syncthreads();
    for (int i = wrow; i < 32; i += 8) {
        int n = n0 + i;
        float x = tile[lane][i];
        __nv_bfloat16 h = __float2bfloat16(x);
        g_WtaT_hi[(long)n * cCAT + k0 + lane] = h;
        g_WtaT_lo[(long)n * cCAT + k0 + lane] = __float2bfloat16(x - __bfloat162float(h));
    }
}

// W1 (4608x1024) -> e/a packs (1024x2304), rows reordered; z selects pack:
//   z=0 e: [H_ (seg0), A_h2h (seg3), tokArgAw (seg2)]
//   z=1 a: [arg (seg1), A_u2u (seg5), argTokAw (seg4)]
__global__ void tr_w1_kernel(const float* __restrict__ W1, int z) {
    __shared__ float tile[32][33];
    int r0 = blockIdx.x * 32, n0 = blockIdx.y * 32;
    int lane = threadIdx.x & 31, wrow = threadIdx.x >> 5;
    for (int i = wrow; i < 32; i += 8) {
        int r = r0 + i;
        int src;
        if (z == 0) src = (r < cD) ? r : ((r < 2 * cD) ? r + 2 * cD : r);
        else        src = (r < cD) ? r + cD : ((r < 2 * cD) ? r + 4 * cD : r + 2 * cD);
        tile[i][lane] = W1[(long)src * cNHID + n0 + lane];
    }
    __syncthreads();
    __nv_bfloat16* Bh = z ? g_W1aT_hi : g_W1eT_hi;
    __nv_bfloat16* Bl = z ? g_W1aT_lo : g_W1eT_lo;
    for (int i = wrow; i < 32; i += 8) {
        int n = n0 + i;
        float x = tile[lane][i];
        __nv_bfloat16 h = __float2bfloat16(x);
        Bh[(long)n * cCAT + r0 + lane] = h;
        Bl[(long)n * cCAT + r0 + lane] = __float2bfloat16(x - __bfloat162float(h));
    }
}

// ---------------- gather masked sentence embeddings ----------------
__global__ void gather_kernel(const float* __restrict__ emb) {
    int s = blockIdx.x, b = blockIdx.y;
    int ns = g_nsent[b];
    int idx = g_idx[b * cS + s];
    bool valid = (s < ns);
    const float* src = emb + ((long)b * cL + idx) * cD;
    float* dst = g_sent_emb + ((long)b * cS + s) * cD;
    for (int d = threadIdx.x; d < cD; d += blockDim.x)
        dst[d] = valid ? src[d] : 0.f;
}

// -------- fused entity + trig + ent_cat build + nonempty (compacted index loop) -----
__global__ void entity_fused_kernel(const float* __restrict__ emb,
                                    const float* __restrict__ entmap,
                                    const float* __restrict__ istr) {
    int e = blockIdx.x, b = blockIdx.y;
    __shared__ float w[cS], tw[cS];
    __shared__ int sidx[cS];
    __shared__ int act[cS];
    __shared__ int nact_s;
    __shared__ float red[256];
    __shared__ float tsum_s;
    int tid = threadIdx.x;
    int ns = g_nsent[b];
    if (tid < cS) {
        bool v = tid < ns;
        w[tid] = v ? entmap[((long)b * cS + tid) * cE + e] : 0.f;
        tw[tid] = v ? istr[b * cS + tid] : 0.f;
        sidx[tid] = g_idx[b * cS + tid];
    }
    __syncthreads();
    if (tid == 0) {
        float s = 0.f;
        for (int i = 0; i < cS; i++) s += istr[b * cS + i];
        tsum_s = s;
        int n = 0;
        for (int s2 = 0; s2 < cS; s2++)
            if (w[s2] != 0.f || tw[s2] != 0.f) act[n++] = s2;
        nact_s = n;
    }
    __syncthreads();
    int nact = nact_s;
    float ea[3] = {0.f, 0.f, 0.f}, ta[3] = {0.f, 0.f, 0.f};
    for (int k = 0; k < nact; k++) {
        int s = act[k];
        float ws = w[s], ts = tw[s];
        const float* row = emb + ((long)b * cL + sidx[s]) * cD;
        float x0 = row[tid], x1 = row[tid + 256], x2 = row[tid + 512];
        ea[0] += ws * x0; ea[1] += ws * x1; ea[2] += ws * x2;
        ta[0] += ts * x0; ta[1] += ts * x1; ta[2] += ts * x2;
    }
    float inv = 1.f / tsum_s;
    int r = b * cE + e;
    float asum = 0.f;
#pragma unroll
    for (int j = 0; j < 3; j++) {
        float en = ea[j];
        float tg = ta[j] * inv;
        g_entcat[(long)r * cCAT + j * 256 + tid] = en;
        g_entcat[(long)r * cCAT + cD + j * 256 + tid] = tg;
        g_entcat[(long)r * cCAT + 2 * cD + j * 256 + tid] = en * tg;
        g_cat_e[(long)r * cCAT + j * 256 + tid] = en;   // cat_e seg0 (entity)
        asum += fabsf(en);
    }
    red[tid] = asum;
    __syncthreads();
    for (int st = 128; st > 0; st >>= 1) {
        if (tid < st) red[tid] += red[tid + st];
        __syncthreads();
    }
    if (tid == 0) g_nonempty[r] = (red[0] > 0.f) ? 1.f : 0.f;
}

// ---------------- arg = arg_emb0^T @ arg_w  (into cat_a seg0) ----------------
__global__ void arg_kernel(const float* __restrict__ emb, const float* __restrict__ argw) {
    int a = blockIdx.x, b = blockIdx.y;
    __shared__ float wl[cLA];
    __shared__ int pl[cLA];
    int tid = threadIdx.x;
    if (tid < cLA) {
        int pos = g_sls[b] + 1 + tid;
        bool v = pos < g_blen[b] - 1;
        int pc = min(max(pos, 0), cL - 1);
        pl[tid] = pc;
        wl[tid] = v ? argw[((long)b * cLA + tid) * cNA + a] : 0.f;
    }
    __syncthreads();
    for (int d = tid; d < cD; d += blockDim.x) {
        float acc = 0.f;
        for (int l = 0; l < cLA; l++) {
            float w = wl[l];
            if (w != 0.f) acc += w * emb[((long)b * cL + pl[l]) * cD + d];
        }
        g_cat_a[((long)(b * cNA + a)) * cCAT + d] = acc;
    }
}

// ---------------- small SIMT GEMM (t2t @ sent_emb) ----------------
__global__ __launch_bounds__(256) void gemm_small_kernel(
    const float* __restrict__ A, const float* __restrict__ Bm, float* __restrict__ C,
    int M, int N, int K, long sA, long sB, long sC) {
    int z = blockIdx.z;
    A += (long)z * sA; Bm += (long)z * sB; C += (long)z * sC;
    int bm = blockIdx.y * 64, bn = blockIdx.x * 64;
    __shared__ float As[16 * 64];
    __shared__ float Bs[16 * 64];
    int tid = threadIdx.x;
    int tx = tid & 15, ty = tid >> 4;
    float acc[4][4] = {};
    int ktiles = (K + 15) >> 4;
    for (int kt = 0; kt < ktiles; kt++) {
        int k0 = kt * 16;
#pragma unroll
        for (int i = 0; i < 4; i++) {
            int e = tid + i * 256;
            int m = e >> 4, kk = e & 15;
            float av = 0.f;
            if (bm + m < M && k0 + kk < K) av = A[(long)(bm + m) * K + k0 + kk];
            As[kk * 64 + m] = av;
            int k2 = e >> 6, n2 = e & 63;
            float bv = 0.f;
            if (k0 + k2 < K && bn + n2 < N) bv = Bm[(long)(k0 + k2) * N + bn + n2];
            Bs[k2 * 64 + n2] = bv;
        }
        __syncthreads();
#pragma unroll
        for (int k = 0; k < 16; k++) {
            float4 a4 = *(const float4*)&As[k * 64 + ty * 4];
            float4 b4 = *(const float4*)&Bs[k * 64 + tx * 4];
            float av[4] = {a4.x, a4.y, a4.z, a4.w};
            float bv[4] = {b4.x, b4.y, b4.z, b4.w};
#pragma unroll
            for (int i = 0; i < 4; i++)
#pragma unroll
                for (int j = 0; j < 4; j++) acc[i][j] += av[i] * bv[j];
        }
        __syncthreads();
    }
#pragma unroll
    for (int i = 0; i < 4; i++) {
        int r = bm + ty * 4 + i;
        if (r >= M) continue;
#pragma unroll
        for (int j = 0; j < 4; j++) {
            int c = bn + tx * 4 + j;
            if (c < N) C[(long)r * N + c] = acc[i][j];
        }
    }
}

// ---- fused: score = entity2 . arg / sqrt(D); row-L1-norm; toka -> cat_e seg2 ----
__global__ void score_toka_kernel() {
    int e = blockIdx.x, b = blockIdx.y;
    __shared__ float er[cD];
    __shared__ float tw[cNA];
    int tid = threadIdx.x;
    int r = b * cE + e;
    for (int d = tid; d < cD; d += 256) er[d] = g_entity2[(long)r * cD + d];
    __syncthreads();
    int w = tid >> 5, lane = tid & 31;
#pragma unroll
    for (int j = 0; j < 4; j++) {
        int a = w * 4 + j;
        const float* ar = g_cat_a + ((long)(b * cNA + a)) * cCAT;
        float p = 0.f;
        for (int d = lane; d < cD; d += 32) p += er[d] * ar[d];
#pragma unroll
        for (int off = 16; off > 0; off >>= 1) p += __shfl_xor_sync(0xffffffffu, p, off);
        if (lane == 0) {
            float sc = p * RSQRTD;
            g_score[r * cNA + a] = sc;
            tw[a] = sc;
        }
    }
    __syncthreads();
    if (tid < cNA) {
        float v = tw[tid];
        float s = fabsf(v);
#pragma unroll
        for (int off = 16; off > 0; off >>= 1) s += __shfl_xor_sync(0xffffffffu, s, off);
        tw[tid] = v / fmaxf(s, EPSV);
    }
    __syncthreads();
    for (int d = tid; d < cD; d += 256) {
        float acc = 0.f;
        for (int a = 0; a < cNA; a++) acc += tw[a] * g_cat_a[((long)(b * cNA + a)) * cCAT + d];
        g_cat_e[(long)r * cCAT + 2 * cD + d] = acc;   // cat_e seg2 (toka)
    }
}

// ---------------- arg_tokenAwared (cat_a seg2) with fused col-L1-norm ----------------
__global__ void argtok_kernel() {
    int a = blockIdx.x, b = blockIdx.y;
    __shared__ float col[cE];
    __shared__ float red[8];
    int tid = threadIdx.x, wid = tid >> 5, lane = tid & 31;
    float v = 0.f;
    if (tid < cE) v = g_score[(b * cE + tid) * cNA + a];
    float s = fabsf(v);
#pragma unroll
    for (int off = 16; off > 0; off >>= 1) s += __shfl_xor_sync(0xffffffffu, s, off);
    if (lane == 0) red[wid] = s;
    __syncthreads();
    if (tid == 0) red[0] = fmaxf(red[0] + red[1], EPSV);
    __syncthreads();
    if (tid < cE) col[tid] = v / red[0];
    __syncthreads();
    for (int d = tid; d < cD; d += 256) {
        float acc = 0.f;
        for (int e = 0; e < cE; e++) acc += col[e] * g_entity2[((long)(b * cE + e)) * cD + d];
        g_cat_a[((long)(b * cNA + a)) * cCAT + 2 * cD + d] = acc;   // cat_a seg2
    }
}

// ------- gathered attention avg: 256 threads, 2-way head split, early-out -------
__global__ void __launch_bounds__(256)
t2t_kernel(const float* __restrict__ att0, const float* __restrict__ att1,
           const float* __restrict__ att2) {
    int s = blockIdx.x, b = blockIdx.y;
    int tid = threadIdx.x;  // 256
    int ns = g_nsent[b];
    if (s >= ns) {
        if (tid < cS) g_t2t[((long)b * cS + s) * cS + tid] = 0.f;
        return;
    }
    __shared__ int sj[cS];
    __shared__ float acc[3][2][cL];
    __shared__ float red0[256], red1[256], red2[256];
    if (tid < cS) sj[tid] = g_idx[b * cS + tid];
    __syncthreads();
    int i = sj[s];
    int col = tid & 127, grp = tid >> 7;   // grp 0: heads 0-5, grp 1: heads 6-11
    float a00 = 0.f, a01 = 0.f, a10 = 0.f, a11 = 0.f, a20 = 0.f, a21 = 0.f;
    int h0 = grp * 6;
#pragma unroll
    for (int hh = 0; hh < 6; hh++) {
        int h = h0 + hh;
        long rb = (((long)(b * cH + h)) * cL + i) * cL;
        float2 v0 = *(const float2*)(att0 + rb + 2 * col);
        float2 v1 = *(const float2*)(att1 + rb + 2 * col);
        float2 v2 = *(const float2*)(att2 + rb + 2 * col);
        a00 += v0.x; a01 += v0.y;
        a10 += v1.x; a11 += v1.y;
        a20 += v2.x; a21 += v2.y;
    }
    acc[0][grp][2 * col] = a00; acc[0][grp][2 * col + 1] = a01;
    acc[1][grp][2 * col] = a10; acc[1][grp][2 * col + 1] = a11;
    acc[2][grp][2 * col] = a20; acc[2][grp][2 * col + 1] = a21;
    __syncthreads();
    float v0 = 0.f, v1 = 0.f, v2 = 0.f;
    if (tid < ns) {
        int j = sj[tid];
        v0 = acc[0][0][j] + acc[0][1][j];
        v1 = acc[1][0][j] + acc[1][1][j];
        v2 = acc[2][0][j] + acc[2][1][j];
    }
    red0[tid] = v0; red1[tid] = v1; red2[tid] = v2;
    __syncthreads();
    for (int st = 128; st > 0; st >>= 1) {
        if (tid < st) {
            red0[tid] += red0[tid + st];
            red1[tid] += red1[tid + st];
            red2[tid] += red2[tid + st];
        }
        __syncthreads();
    }
    float r0 = fmaxf(red0[0], EPSV), r1 = fmaxf(red1[0], EPSV), r2 = fmaxf(red2[0], EPSV);
    if (tid < cS)
        g_t2t[((long)b * cS + s) * cS + tid] = (v0 / r0 + v1 / r1 + v2 / r2) * (1.f / 3.f);
}

// ---------------- A_h2h = entmap^T @ a_h2h_tok (cat_e seg1, compacted) ----------------
__global__ void ahh_map_kernel(const float* __restrict__ entmap) {
    int e = blockIdx.x, b = blockIdx.y;
    __shared__ float w[cS];
    __shared__ int act[cS];
    __shared__ int nact_s;
    int tid = threadIdx.x;
    if (tid < cS) {
        bool v = tid < g_nsent[b];
        w[tid] = v ? entmap[((long)b * cS + tid) * cE + e] : 0.f;
    }
    __syncthreads();
    if (tid == 0) {
        int n = 0;
        for (int s = 0; s < cS; s++)
            if (w[s] != 0.f) act[n++] = s;
        nact_s = n;
    }
    __syncthreads();
    int nact = nact_s;
    float acc[3] = {0.f, 0.f, 0.f};
    for (int k = 0; k < nact; k++) {
        int s = act[k];
        float ws = w[s];
        const float* row = g_ahh + ((long)b * cS + s) * cD;
        acc[0] += ws * row[tid];
        acc[1] += ws * row[tid + 256];
        acc[2] += ws * row[tid + 512];
    }
    int r = b * cE + e;
#pragma unroll
    for (int j = 0; j < 3; j++)
        g_cat_e[(long)r * cCAT + cD + j * 256 + tid] = acc[j];   // cat_e seg1
}

// ---------------- a2a = softmax(arg @ arg^T) ----------------
__global__ void a2a_kernel() {
    int a = blockIdx.x, b = blockIdx.y;
    int lane = threadIdx.x;
    float af[24];
    const float* me = g_cat_a + ((long)(b * cNA + a)) * cCAT;
#pragma unroll
    for (int k = 0; k < 24; k++) af[k] = me[lane + 32 * k];
    float myv = 0.f;
    for (int a2 = 0; a2 < cNA; a2++) {
        const float* r = g_cat_a + ((long)(b * cNA + a2)) * cCAT;
        float s = 0.f;
#pragma unroll
        for (int k = 0; k < 24; k++) s += af[k] * r[lane + 32 * k];
#pragma unroll
        for (int off = 16; off > 0; off >>= 1) s += __shfl_xor_sync(0xffffffffu, s, off);
        if (a2 == lane) myv = s;
    }
    float m = myv;
#pragma unroll
    for (int off = 16; off > 0; off >>= 1) m = fmaxf(m, __shfl_xor_sync(0xffffffffu, m, off));
    float p = expf(myv - m);
    float sum = p;
#pragma unroll
    for (int off = 16; off > 0; off >>= 1) sum += __shfl_xor_sync(0xffffffffu, sum, off);
    g_a2a[(b * cNA + a) * cNA + lane] = p / sum;
}

// ---------------- A_u2u = a2a @ arg (cat_a seg1) ----------------
__global__ void au2u_kernel() {
    int a = blockIdx.x, b = blockIdx.y;
    __shared__ float p_s[cNA];
    int tid = threadIdx.x;
    if (tid < cNA) p_s[tid] = g_a2a[(b * cNA + a) * cNA + tid];
    __syncthreads();
    for (int d = tid; d < cD; d += 256) {
        float acc = 0.f;
        for (int a2 = 0; a2 < cNA; a2++)
            acc += p_s[a2] * g_cat_a[((long)(b * cNA + a2)) * cCAT + d];
        g_cat_a[((long)(b * cNA + a)) * cCAT + cD + d] = acc;   // cat_a seg1
    }
}

// ---------------- final: out = gelu(Pe + Pa) @ W2 + b2 ----------------
__device__ __forceinline__ float gelu_exact(float x) {
    return 0.5f * x * (1.f + erff(x * 0.70710678118654752f));
}

__global__ __launch_bounds__(256) void final_kernel(const float* __restrict__ W2,
                                                    const float* __restrict__ b2,
                                                    float* __restrict__ out) {
    int be = blockIdx.x;
    int b = be >> 6;
    __shared__ float pe_s[cNHID];
    __shared__ float w2_s[cNHID];
    int tid = threadIdx.x;
    for (int n = tid; n < cNHID; n += 256) {
        pe_s[n] = g_Pe[(long)be * cNHID + n];
        w2_s[n] = W2[n];
    }
    __syncthreads();
    int w = tid >> 5, lane = tid & 31;
    const float* pa = g_Pa + ((long)(b * cNA + w * 4)) * cNHID;
    float acc0 = 0.f, acc1 = 0.f, acc2 = 0.f, acc3 = 0.f;
    for (int k = 0; k < 32; k++) {
        int n = lane + 32 * k;
        float pe = pe_s[n], w2 = w2_s[n];
        acc0 += gelu_exact(pe + pa[n]) * w2;
        acc1 += gelu_exact(pe + pa[cNHID + n]) * w2;
        acc2 += gelu_exact(pe + pa[2 * cNHID + n]) * w2;
        acc3 += gelu_exact(pe + pa[3 * cNHID + n]) * w2;
    }
#pragma unroll
    for (int off = 16; off > 0; off >>= 1) {
        acc0 += __shfl_xor_sync(0xffffffffu, acc0, off);
        acc1 += __shfl_xor_sync(0xffffffffu, acc1, off);
        acc2 += __shfl_xor_sync(0xffffffffu, acc2, off);
        acc3 += __shfl_xor_sync(0xffffffffu, acc3, off);
    }
    if (lane == 0) {
        float bb = b2[0];
        out[(long)be * cNA + w * 4 + 0] = acc0 + bb;
        out[(long)be * cNA + w * 4 + 1] = acc1 + bb;
        out[(long)be * cNA + w * 4 + 2] = acc2 + bb;
        out[(long)be * cNA + w * 4 + 3] = acc3 + bb;
    }
}

// ---------------- host launcher (multi-stream fork/join, capture-safe) ------------
static cudaStream_t hs1, hs2, hs3;
static cudaEvent_t hevRoot, hevMeta, hevEnt, hevWta, hevAhh, hevArg0, hevScore,
                   hevPe01, hevPa;
static bool h_init_done = false;

extern "C" void kernel_launch(void* const* d_in, const int* in_sizes, int n_in,
                              void* d_out, int out_size) {
    const float* emb    = (const float*)d_in[0];
    const float* istr   = (const float*)d_in[1];
    const float* argw   = (const float*)d_in[2];
    const float* entmap = (const float*)d_in[3];
    const float* att0   = (const float*)d_in[4];
    const float* att1   = (const float*)d_in[5];
    const float* att2   = (const float*)d_in[6];
    const float* W_ta   = (const float*)d_in[7];
    const float* b_ta   = (const float*)d_in[8];
    const float* W1     = (const float*)d_in[9];
    const float* b1     = (const float*)d_in[10];
    const float* W2     = (const float*)d_in[11];
    const float* b2     = (const float*)d_in[12];
    const void*  idxs   = d_in[13];
    const void*  blen   = d_in[14];
    float* out = (float*)d_out;

    float *p_entcat, *p_entity2, *p_nonempty, *p_cat_e, *p_cat_a;
    float *p_Pe, *p_Pa, *p_t2t, *p_sent, *p_ahh;
    __nv_bfloat16 *p_WtaH, *p_WtaL, *p_W1eH, *p_W1eL, *p_W1aH, *p_W1aL;
    cudaGetSymbolAddress((void**)&p_entcat, g_entcat);
    cudaGetSymbolAddress((void**)&p_entity2, g_entity2);
    cudaGetSymbolAddress((void**)&p_nonempty, g_nonempty);
    cudaGetSymbolAddress((void**)&p_cat_e, g_cat_e);
    cudaGetSymbolAddress((void**)&p_cat_a, g_cat_a);
    cudaGetSymbolAddress((void**)&p_Pe, g_Pe);
    cudaGetSymbolAddress((void**)&p_Pa, g_Pa);
    cudaGetSymbolAddress((void**)&p_t2t, g_t2t);
    cudaGetSymbolAddress((void**)&p_sent, g_sent_emb);
    cudaGetSymbolAddress((void**)&p_ahh, g_ahh);
    cudaGetSymbolAddress((void**)&p_WtaH, g_WtaT_hi);
    cudaGetSymbolAddress((void**)&p_WtaL, g_WtaT_lo);
    cudaGetSymbolAddress((void**)&p_W1eH, g_W1eT_hi);
    cudaGetSymbolAddress((void**)&p_W1eL, g_W1eT_lo);
    cudaGetSymbolAddress((void**)&p_W1aH, g_W1aT_hi);
    cudaGetSymbolAddress((void**)&p_W1aL, g_W1aT_lo);

    if (!h_init_done) {
        cudaFuncSetAttribute(mma_gemm_kernel,
                             cudaFuncAttributeMaxDynamicSharedMemorySize, GM_SMEM);
        cudaStreamCreateWithFlags(&hs1, cudaStreamNonBlocking);
        cudaStreamCreateWithFlags(&hs2, cudaStreamNonBlocking);
        cudaStreamCreateWithFlags(&hs3, cudaStreamNonBlocking);
        cudaEventCreateWithFlags(&hevRoot, cudaEventDisableTiming);
        cudaEventCreateWithFlags(&hevMeta, cudaEventDisableTiming);
        cudaEventCreateWithFlags(&hevEnt, cudaEventDisableTiming);
        cudaEventCreateWithFlags(&hevWta, cudaEventDisableTiming);
        cudaEventCreateWithFlags(&hevAhh, cudaEventDisableTiming);
        cudaEventCreateWithFlags(&hevArg0, cudaEventDisableTiming);
        cudaEventCreateWithFlags(&hevScore, cudaEventDisableTiming);
        cudaEventCreateWithFlags(&hevPe01, cudaEventDisableTiming);
        cudaEventCreateWithFlags(&hevPa, cudaEventDisableTiming);
        meta_kernel<<<1, cB, 0, hs1>>>(idxs, blen);
        meta_kernel<<<1, cB, 0, hs2>>>(idxs, blen);
        meta_kernel<<<1, cB, 0, hs3>>>(idxs, blen);
        cudaStreamSynchronize(hs1);
        cudaStreamSynchronize(hs2);
        cudaStreamSynchronize(hs3);
        h_init_done = true;
    }
    cudaStream_t s1 = hs1, s2 = hs2, s3 = hs3;

    // ---- fork: weight prep. s2: Wta + W1 e-pack (gates GEMM1/Pe01 by stream order)
    cudaEventRecord(hevRoot, 0);
    cudaStreamWaitEvent(s2, hevRoot, 0);
    tr_wta_kernel<<<dim3(cCAT / 32, cD / 32), 256, 0, s2>>>(W_ta);
    cudaEventRecord(hevWta, s2);
    tr_w1_kernel<<<dim3(cCAT / 32, cNHID / 32), 256, 0, s2>>>(W1, 0);

    // ---- main: meta, entity ----
    meta_kernel<<<1, cB>>>(idxs, blen);
    cudaEventRecord(hevMeta, 0);
    entity_fused_kernel<<<dim3(cE, cB), 256>>>(emb, entmap, istr);
    cudaEventRecord(hevEnt, 0);

    // ---- s1: t2t chain ----
    cudaStreamWaitEvent(s1, hevMeta, 0);
    gather_kernel<<<dim3(cS, cB), 256, 0, s1>>>(emb);
    t2t_kernel<<<dim3(cS, cB), 256, 0, s1>>>(att0, att1, att2);
    gemm_small_kernel<<<dim3((cD + 63) / 64, (cS + 63) / 64, cB), 256, 0, s1>>>(
        p_t2t, p_sent, p_ahh, cS, cD, cS,
        (long)cS * cS, (long)cS * cD, (long)cS * cD);
    ahh_map_kernel<<<dim3(cE, cB), 256, 0, s1>>>(entmap);
    cudaEventRecord(hevAhh, s1);

    // ---- s3: arg chain (cat_a seg0, seg1) + W1 a-pack ----
    cudaStreamWaitEvent(s3, hevMeta, 0);
    arg_kernel<<<dim3(cNA, cB), 256, 0, s3>>>(emb, argw);
    cudaEventRecord(hevArg0, s3);
    a2a_kernel<<<dim3(cNA, cB), 32, 0, s3>>>();
    au2u_kernel<<<dim3(cNA, cB), 256, 0, s3>>>();
    tr_w1_kernel<<<dim3(cCAT / 32, cNHID / 32), 256, 0, s3>>>(W1, 1);

    // ---- main: GEMM1 (entity2, full K) — gated only by tr_wta ----
    cudaStreamWaitEvent(0, hevWta, 0);
    mma_gemm_kernel<<<dim3(cD / 128, (cB * cE) / 128), 256, GM_SMEM>>>(
        p_entcat, p_WtaH, p_WtaL, p_entity2, cB * cE, cD, cCAT, cCAT, cCAT,
        b_ta, p_nonempty, 0);

    // ---- s2: Pe seg01 (K=1536: entity+ahh); W1e ready by stream order ----
    cudaStreamWaitEvent(s2, hevEnt, 0);
    cudaStreamWaitEvent(s2, hevAhh, 0);
    mma_gemm_kernel<<<dim3(cNHID / 128, (cB * cE) / 128), 256, GM_SMEM, s2>>>(
        p_cat_e, p_W1eH, p_W1eL, p_Pe, cB * cE, cNHID, 2 * cD, cCAT, cCAT,
        b1, nullptr, 0);
    cudaEventRecord(hevPe01, s2);

    // ---- s3: Pa seg01 (K=1536: arg+au2u); W1a ready by stream order ----
    mma_gemm_kernel<<<dim3(cNHID / 128, (cB * cNA) / 128), 256, GM_SMEM, s3>>>(
        p_cat_a, p_W1aH, p_W1aL, p_Pa, cB * cNA, cNHID, 2 * cD, cCAT, cCAT,
        nullptr, nullptr, 0);

    // ---- main: fused score+toka ----
    cudaStreamWaitEvent(0, hevArg0, 0);
    score_toka_kernel<<<dim3(cE, cB), 256>>>();
    cudaEventRecord(hevScore, 0);

    // ---- s3: argtok + Pa seg2 (K=768, accum) ----
    cudaStreamWaitEvent(s3, hevScore, 0);
    argtok_kernel<<<dim3(cNA, cB), 256, 0, s3>>>();
    mma_gemm_kernel<<<dim3(cNHID / 128, (cB * cNA) / 128), 256, GM_SMEM, s3>>>(
        p_cat_a + 2 * cD, p_W1aH + 2 * cD, p_W1aL + 2 * cD, p_Pa,
        cB * cNA, cNHID, cD, cCAT, cCAT, nullptr, nullptr, 1);
    cudaEventRecord(hevPa, s3);

    // ---- main: Pe seg2 (K=768, accum) + final ----
    cudaStreamWaitEvent(0, hevPe01, 0);
    mma_gemm_kernel<<<dim3(cNHID / 128, (cB * cE) / 128), 256, GM_SMEM>>>(
        p_cat_e + 2 * cD, p_W1eH + 2 * cD, p_W1eL + 2 * cD, p_Pe,
        cB * cE, cNHID, cD, cCAT, cCAT, nullptr, nullptr, 1);
    cudaStreamWaitEvent(0, hevPa, 0);
    final_kernel<<<cB * cE, 256>>>(W2, b2, out);
}

// round 17
// speedup vs baseline: 1.0537x; 1.0537x over previous
#include <cuda_runtime.h>
#include <cuda_bf16.h>
#include <math.h>
#include <stdint.h>

// ---------------- problem constants ----------------
constexpr int cB = 16, cL = 256, cS = 100, cLA = 48, cNA = 32, cE = 64;
constexpr int cD = 768, cH = 12, cNHID = 1024, cW = 102, cCAT = 3 * cD; // 2304
#define EPSV 1e-12f
#define RSQRTD 0.03608439182435161f   // 1/sqrt(768)

// ---------------- device scratch ----------------
// cat_e layout: [entity | ahh | toka]  (score-dependent part LAST)
// cat_a layout: [arg | au2u | argtok]
__device__ float g_sent_emb[cB * cS * cD];
__device__ float g_entcat[cB * cE * cCAT];
__device__ float g_nonempty[cB * cE];
__device__ float g_entity2[cB * cE * cD];
__device__ float g_cat_e[cB * cE * cCAT];
__device__ float g_cat_a[cB * cNA * cCAT];
__device__ float g_score[cB * cE * cNA];
__device__ float g_t2t[cB * cS * cS];
__device__ float g_ahh[cB * cS * cD];
__device__ float g_a2a[cB * cNA * cNA];
__device__ float g_Pe[cB * cE * cNHID];
__device__ float g_Pa[cB * cNA * cNHID];
__device__ int   g_idx[cB * cS];
__device__ int   g_nsent[cB];
__device__ int   g_sls[cB];
__device__ int   g_blen[cB];
// bf16 split weight packs (N x K layouts, rows reordered to match cat_e/cat_a)
__device__ __nv_bfloat16 g_WtaT_hi[cD * cCAT];
__device__ __nv_bfloat16 g_WtaT_lo[cD * cCAT];
__device__ __nv_bfloat16 g_W1eT_hi[cNHID * cCAT];
__device__ __nv_bfloat16 g_W1eT_lo[cNHID * cCAT];
__device__ __nv_bfloat16 g_W1aT_hi[cNHID * cCAT];
__device__ __nv_bfloat16 g_W1aT_lo[cNHID * cCAT];

// ================= mma.sync helpers =================
__device__ __forceinline__ uint32_t smem_to_u32(const void* p) {
    uint32_t a;
    asm("{ .reg .u64 t; cvta.to.shared.u64 t, %1; cvt.u32.u64 %0, t; }"
        : "=r"(a) : "l"(p));
    return a;
}
__device__ __forceinline__ void ldsm4(uint32_t (&r)[4], uint32_t addr) {
    asm volatile("ldmatrix.sync.aligned.m8n8.x4.shared.b16 {%0,%1,%2,%3}, [%4];"
        : "=r"(r[0]), "=r"(r[1]), "=r"(r[2]), "=r"(r[3]) : "r"(addr));
}
__device__ __forceinline__ void mma16816(float (&d)[4], const uint32_t (&a)[4],
                                         uint32_t b0, uint32_t b1) {
    asm volatile(
        "mma.sync.aligned.m16n8k16.row.col.f32.bf16.bf16.f32 "
        "{%0,%1,%2,%3}, {%4,%5,%6,%7}, {%8,%9}, {%0,%1,%2,%3};"
        : "+f"(d[0]), "+f"(d[1]), "+f"(d[2]), "+f"(d[3])
        : "r"(a[0]), "r"(a[1]), "r"(a[2]), "r"(a[3]), "r"(b0), "r"(b1));
}

// ================= split-bf16 tensor GEMM: C(MxN) (+)= A(MxK fp32, lda) @ B^T (NxK bf16 hi/lo, ldb)
// block tile 128x128, 8 warps (2m x 4n, warp tile 64x32), K-chunk 32, double buffer.
constexpr int GM_ASTR = 40;                       // bf16 per smem row (pad 32->40)
constexpr int GM_OFF_AH = 0;
constexpr int GM_OFF_AL = 128 * GM_ASTR * 2;      // 10240
constexpr int GM_OFF_BH = 2 * GM_OFF_AL;          // 20480
constexpr int GM_OFF_BL = GM_OFF_BH + 128 * GM_ASTR * 2;   // 30720
constexpr int GM_BUF_BYTES = GM_OFF_BL + 128 * GM_ASTR * 2; // 40960
constexpr int GM_SMEM = 2 * GM_BUF_BYTES;         // 81920

__global__ void __launch_bounds__(256, 1)
mma_gemm_kernel(const float* __restrict__ A,
                const __nv_bfloat16* __restrict__ Bhi,
                const __nv_bfloat16* __restrict__ Blo,
                float* __restrict__ C, int M, int N, int K, int lda, int ldb,
                const float* __restrict__ bias, const float* __restrict__ rowscale,
                int accum) {
    extern __shared__ char smem[];
    uint32_t sbase = smem_to_u32(smem);
    int tid = threadIdx.x, wid = tid >> 5, lane = tid & 31;
    int wm = wid >> 2, wn = wid & 3;
    int bm = blockIdx.y * 128, bn = blockIdx.x * 128;

    float acc[4][4][4];
#pragma unroll
    for (int i = 0; i < 4; i++)
#pragma unroll
        for (int j = 0; j < 4; j++)
#pragma unroll
            for (int q = 0; q < 4; q++) acc[i][j][q] = 0.f;

    int nch = K >> 5;
    float4 aReg[4];
    uint4 bhReg[2], blReg[2];

    auto gload = [&](int c) {
        int k0 = c << 5;
#pragma unroll
        for (int i = 0; i < 4; i++) {
            int idx = tid + i * 256;
            int row = idx >> 3, c4 = idx & 7;
            aReg[i] = *(const float4*)(A + (long)(bm + row) * lda + k0 + c4 * 4);
        }
#pragma unroll
        for (int i = 0; i < 2; i++) {
            int idx = tid + i * 256;
            int row = idx >> 2, c16 = idx & 3;
            long off = (long)(bn + row) * ldb + k0 + c16 * 8;
            bhReg[i] = *(const uint4*)(Bhi + off);
            blReg[i] = *(const uint4*)(Blo + off);
        }
    };
    auto sstore = [&](int buf) {
        char* base = smem + buf * GM_BUF_BYTES;
#pragma unroll
        for (int i = 0; i < 4; i++) {
            int idx = tid + i * 256;
            int row = idx >> 3, c4 = idx & 7;
            float4 v = aReg[i];
            __nv_bfloat162 h01 = __floats2bfloat162_rn(v.x, v.y);
            __nv_bfloat162 h23 = __floats2bfloat162_rn(v.z, v.w);
            __nv_bfloat162 l01 = __floats2bfloat162_rn(v.x - __bfloat162float(h01.x),
                                                       v.y - __bfloat162float(h01.y));
            __nv_bfloat162 l23 = __floats2bfloat162_rn(v.z - __bfloat162float(h23.x),
                                                       v.w - __bfloat162float(h23.y));
            uint2 H, Lo;
            H.x = *(uint32_t*)&h01; H.y = *(uint32_t*)&h23;
            Lo.x = *(uint32_t*)&l01; Lo.y = *(uint32_t*)&l23;
            *(uint2*)(base + GM_OFF_AH + row * (GM_ASTR * 2) + c4 * 8) = H;
            *(uint2*)(base + GM_OFF_AL + row * (GM_ASTR * 2) + c4 * 8) = Lo;
        }
#pragma unroll
        for (int i = 0; i < 2; i++) {
            int idx = tid + i * 256;
            int row = idx >> 2, c16 = idx & 3;
            *(uint4*)(base + GM_OFF_BH + row * (GM_ASTR * 2) + c16 * 16) = bhReg[i];
            *(uint4*)(base + GM_OFF_BL + row * (GM_ASTR * 2) + c16 * 16) = blReg[i];
        }
    };
    auto compute = [&](int buf) {
        uint32_t sb = sbase + buf * GM_BUF_BYTES;
#pragma unroll
        for (int kk = 0; kk < 32; kk += 16) {
            uint32_t ah[4][4], al[4][4];
#pragma unroll
            for (int mf = 0; mf < 4; mf++) {
                uint32_t off = ((wm * 64 + mf * 16 + (lane & 15)) * GM_ASTR +
                                kk + ((lane >> 4) << 3)) * 2;
                ldsm4(ah[mf], sb + GM_OFF_AH + off);
                ldsm4(al[mf], sb + GM_OFF_AL + off);
            }
            uint32_t bh[2][4], bl[2][4];
#pragma unroll
            for (int p = 0; p < 2; p++) {
                int row = wn * 32 + p * 16 + (lane & 7) + ((lane >> 4) << 3);
                int col = kk + (((lane >> 3) & 1) << 3);
                uint32_t off = (row * GM_ASTR + col) * 2;
                ldsm4(bh[p], sb + GM_OFF_BH + off);
                ldsm4(bl[p], sb + GM_OFF_BL + off);
            }
#pragma unroll
            for (int mf = 0; mf < 4; mf++)
#pragma unroll
                for (int nf = 0; nf < 4; nf++) {
                    uint32_t bh0 = bh[nf >> 1][(nf & 1) * 2];
                    uint32_t bh1 = bh[nf >> 1][(nf & 1) * 2 + 1];
                    uint32_t bl0 = bl[nf >> 1][(nf & 1) * 2];
                    uint32_t bl1 = bl[nf >> 1][(nf & 1) * 2 + 1];
                    mma16816(acc[mf][nf], ah[mf], bh0, bh1);
                    mma16816(acc[mf][nf], ah[mf], bl0, bl1);
                    mma16816(acc[mf][nf], al[mf], bh0, bh1);
                }
        }
    };

    gload(0);
    sstore(0);
    __syncthreads();
    for (int c = 0; c < nch; c++) {
        if (c + 1 < nch) gload(c + 1);
        compute(c & 1);
        __syncthreads();
        if (c + 1 < nch) {
            sstore((c + 1) & 1);
            __syncthreads();
        }
    }
    // epilogue
#pragma unroll
    for (int mf = 0; mf < 4; mf++) {
        int m0 = bm + wm * 64 + mf * 16 + (lane >> 2);
        float rs0 = rowscale ? rowscale[m0] : 1.f;
        float rs1 = rowscale ? rowscale[m0 + 8] : 1.f;
#pragma unroll
        for (int nf = 0; nf < 4; nf++) {
            int n = bn + wn * 32 + nf * 8 + (lane & 3) * 2;
            float b0 = 0.f, b1 = 0.f;
            if (bias) { b0 = bias[n]; b1 = bias[n + 1]; }
            float* c0 = C + (long)m0 * N + n;
            float* c1 = C + (long)(m0 + 8) * N + n;
            float2 v0, v1;
            v0.x = (acc[mf][nf][0] + b0) * rs0;
            v0.y = (acc[mf][nf][1] + b1) * rs0;
            v1.x = (acc[mf][nf][2] + b0) * rs1;
            v1.y = (acc[mf][nf][3] + b1) * rs1;
            if (accum) {
                float2 o0 = *(float2*)c0, o1 = *(float2*)c1;
                v0.x += o0.x; v0.y += o0.y;
                v1.x += o1.x; v1.y += o1.y;
            }
            *(float2*)c0 = v0;
            *(float2*)c1 = v1;
        }
    }
}

// ---------------- meta: decode idxs (int32 or int64), per-b scalars ----------------
__global__ void meta_kernel(const void* idxs_raw, const void* blen_raw) {
    const unsigned* u = (const unsigned*)idxs_raw;
    bool is64 = (u[1] == 0u);
    int b = threadIdx.x;
    if (b >= cB) return;
    int nv = 0;
    for (int i = 0; i < cW; i++) {
        long long v = is64 ? ((const long long*)idxs_raw)[b * cW + i]
                           : (long long)((const int*)idxs_raw)[b * cW + i];
        if (v > 0) nv++;
        if (i < cS) g_idx[b * cS + i] = (int)v;
    }
    int sp = nv - 2;
    long long sls = is64 ? ((const long long*)idxs_raw)[b * cW + sp]
                         : (long long)((const int*)idxs_raw)[b * cW + sp];
    g_nsent[b] = sp;
    g_sls[b] = (int)sls;
    long long bl = is64 ? ((const long long*)blen_raw)[b]
                        : (long long)((const int*)blen_raw)[b];
    g_blen[b] = (int)bl;
}

// ---------------- weight transposes + bf16 hi/lo split ----------------
__global__ void tr_wta_kernel(const float* __restrict__ W) {   // (2304x768) -> (768x2304)
    __shared__ float tile[32][33];
    int k0 = blockIdx.x * 32, n0 = blockIdx.y * 32;
    int lane = threadIdx.x & 31, wrow = threadIdx.x >> 5;
    for (int i = wrow; i < 32; i += 8)
        tile[i][lane] = W[(long)(k0 + i) * cD + n0 + lane];
    __syncthreads();
    for (int i = wrow; i < 32; i += 8) {
        int n = n0 + i;
        float x = tile[lane][i];
        __nv_bfloat16 h = __float2bfloat16(x);
        g_WtaT_hi[(long)n * cCAT + k0 + lane] = h;
        g_WtaT_lo[(long)n * cCAT + k0 + lane] = __float2bfloat16(x - __bfloat162float(h));
    }
}

// W1 (4608x1024) -> e/a packs (1024x2304), rows reordered:
//   e: [H_ (seg0), A_h2h (seg3), tokArgAw (seg2)]
//   a: [arg (seg1), A_u2u (seg5), argTokAw (seg4)]
__global__ void tr_w1_kernel(const float* __restrict__ W1) {
    __shared__ float tile[32][33];
    int z = blockIdx.z;
    int r0 = blockIdx.x * 32, n0 = blockIdx.y * 32;
    int lane = threadIdx.x & 31, wrow = threadIdx.x >> 5;
    for (int i = wrow; i < 32; i += 8) {
        int r = r0 + i;
        int src;
        if (z == 0) src = (r < cD) ? r : ((r < 2 * cD) ? r + 2 * cD : r);
        else        src = (r < cD) ? r + cD : ((r < 2 * cD) ? r + 4 * cD : r + 2 * cD);
        tile[i][lane] = W1[(long)src * cNHID + n0 + lane];
    }
    __syncthreads();
    __nv_bfloat16* Bh = z ? g_W1aT_hi : g_W1eT_hi;
    __nv_bfloat16* Bl = z ? g_W1aT_lo : g_W1eT_lo;
    for (int i = wrow; i < 32; i += 8) {
        int n = n0 + i;
        float x = tile[lane][i];
        __nv_bfloat16 h = __float2bfloat16(x);
        Bh[(long)n * cCAT + r0 + lane] = h;
        Bl[(long)n * cCAT + r0 + lane] = __float2bfloat16(x - __bfloat162float(h));
    }
}

// ---------------- gather masked sentence embeddings ----------------
__global__ void gather_kernel(const float* __restrict__ emb) {
    int s = blockIdx.x, b = blockIdx.y;
    int ns = g_nsent[b];
    int idx = g_idx[b * cS + s];
    bool valid = (s < ns);
    const float* src = emb + ((long)b * cL + idx) * cD;
    float* dst = g_sent_emb + ((long)b * cS + s) * cD;
    for (int d = threadIdx.x; d < cD; d += blockDim.x)
        dst[d] = valid ? src[d] : 0.f;
}

// -------- fused entity + trig + ent_cat build + nonempty (compacted index loop) -----
__global__ void entity_fused_kernel(const float* __restrict__ emb,
                                    const float* __restrict__ entmap,
                                    const float* __restrict__ istr) {
    int e = blockIdx.x, b = blockIdx.y;
    __shared__ float w[cS], tw[cS];
    __shared__ int sidx[cS];
    __shared__ int act[cS];
    __shared__ int nact_s;
    __shared__ float red[256];
    __shared__ float tsum_s;
    int tid = threadIdx.x;
    int ns = g_nsent[b];
    if (tid < cS) {
        bool v = tid < ns;
        w[tid] = v ? entmap[((long)b * cS + tid) * cE + e] : 0.f;
        tw[tid] = v ? istr[b * cS + tid] : 0.f;
        sidx[tid] = g_idx[b * cS + tid];
    }
    __syncthreads();
    if (tid == 0) {
        float s = 0.f;
        for (int i = 0; i < cS; i++) s += istr[b * cS + i];
        tsum_s = s;
        int n = 0;
        for (int s2 = 0; s2 < cS; s2++)
            if (w[s2] != 0.f || tw[s2] != 0.f) act[n++] = s2;
        nact_s = n;
    }
    __syncthreads();
    int nact = nact_s;
    float ea[3] = {0.f, 0.f, 0.f}, ta[3] = {0.f, 0.f, 0.f};
    for (int k = 0; k < nact; k++) {
        int s = act[k];
        float ws = w[s], ts = tw[s];
        const float* row = emb + ((long)b * cL + sidx[s]) * cD;
        float x0 = row[tid], x1 = row[tid + 256], x2 = row[tid + 512];
        ea[0] += ws * x0; ea[1] += ws * x1; ea[2] += ws * x2;
        ta[0] += ts * x0; ta[1] += ts * x1; ta[2] += ts * x2;
    }
    float inv = 1.f / tsum_s;
    int r = b * cE + e;
    float asum = 0.f;
#pragma unroll
    for (int j = 0; j < 3; j++) {
        float en = ea[j];
        float tg = ta[j] * inv;
        g_entcat[(long)r * cCAT + j * 256 + tid] = en;
        g_entcat[(long)r * cCAT + cD + j * 256 + tid] = tg;
        g_entcat[(long)r * cCAT + 2 * cD + j * 256 + tid] = en * tg;
        g_cat_e[(long)r * cCAT + j * 256 + tid] = en;   // cat_e seg0 (entity)
        asum += fabsf(en);
    }
    red[tid] = asum;
    __syncthreads();
    for (int st = 128; st > 0; st >>= 1) {
        if (tid < st) red[tid] += red[tid + st];
        __syncthreads();
    }
    if (tid == 0) g_nonempty[r] = (red[0] > 0.f) ? 1.f : 0.f;
}

// ---------------- arg = arg_emb0^T @ arg_w  (into cat_a seg0) ----------------
__global__ void arg_kernel(const float* __restrict__ emb, const float* __restrict__ argw) {
    int a = blockIdx.x, b = blockIdx.y;
    __shared__ float wl[cLA];
    __shared__ int pl[cLA];
    int tid = threadIdx.x;
    if (tid < cLA) {
        int pos = g_sls[b] + 1 + tid;
        bool v = pos < g_blen[b] - 1;
        int pc = min(max(pos, 0), cL - 1);
        pl[tid] = pc;
        wl[tid] = v ? argw[((long)b * cLA + tid) * cNA + a] : 0.f;
    }
    __syncthreads();
    for (int d = tid; d < cD; d += blockDim.x) {
        float acc = 0.f;
        for (int l = 0; l < cLA; l++) {
            float w = wl[l];
            if (w != 0.f) acc += w * emb[((long)b * cL + pl[l]) * cD + d];
        }
        g_cat_a[((long)(b * cNA + a)) * cCAT + d] = acc;
    }
}

// ---------------- small SIMT GEMM (t2t @ sent_emb) ----------------
__global__ __launch_bounds__(256) void gemm_small_kernel(
    const float* __restrict__ A, const float* __restrict__ Bm, float* __restrict__ C,
    int M, int N, int K, long sA, long sB, long sC) {
    int z = blockIdx.z;
    A += (long)z * sA; Bm += (long)z * sB; C += (long)z * sC;
    int bm = blockIdx.y * 64, bn = blockIdx.x * 64;
    __shared__ float As[16 * 64];
    __shared__ float Bs[16 * 64];
    int tid = threadIdx.x;
    int tx = tid & 15, ty = tid >> 4;
    float acc[4][4] = {};
    int ktiles = (K + 15) >> 4;
    for (int kt = 0; kt < ktiles; kt++) {
        int k0 = kt * 16;
#pragma unroll
        for (int i = 0; i < 4; i++) {
            int e = tid + i * 256;
            int m = e >> 4, kk = e & 15;
            float av = 0.f;
            if (bm + m < M && k0 + kk < K) av = A[(long)(bm + m) * K + k0 + kk];
            As[kk * 64 + m] = av;
            int k2 = e >> 6, n2 = e & 63;
            float bv = 0.f;
            if (k0 + k2 < K && bn + n2 < N) bv = Bm[(long)(k0 + k2) * N + bn + n2];
            Bs[k2 * 64 + n2] = bv;
        }
        __syncthreads();
#pragma unroll
        for (int k = 0; k < 16; k++) {
            float4 a4 = *(const float4*)&As[k * 64 + ty * 4];
            float4 b4 = *(const float4*)&Bs[k * 64 + tx * 4];
            float av[4] = {a4.x, a4.y, a4.z, a4.w};
            float bv[4] = {b4.x, b4.y, b4.z, b4.w};
#pragma unroll
            for (int i = 0; i < 4; i++)
#pragma unroll
                for (int j = 0; j < 4; j++) acc[i][j] += av[i] * bv[j];
        }
        __syncthreads();
    }
#pragma unroll
    for (int i = 0; i < 4; i++) {
        int r = bm + ty * 4 + i;
        if (r >= M) continue;
#pragma unroll
        for (int j = 0; j < 4; j++) {
            int c = bn + tx * 4 + j;
            if (c < N) C[(long)r * N + c] = acc[i][j];
        }
    }
}

// ---- fused: score = entity2 . arg / sqrt(D); row-L1-norm; toka -> cat_e seg2 ----
__global__ void score_toka_kernel() {
    int e = blockIdx.x, b = blockIdx.y;
    __shared__ float er[cD];
    __shared__ float tw[cNA];
    int tid = threadIdx.x;
    int r = b * cE + e;
    for (int d = tid; d < cD; d += 256) er[d] = g_entity2[(long)r * cD + d];
    __syncthreads();
    int w = tid >> 5, lane = tid & 31;
#pragma unroll
    for (int j = 0; j < 4; j++) {
        int a = w * 4 + j;
        const float* ar = g_cat_a + ((long)(b * cNA + a)) * cCAT;
        float p = 0.f;
        for (int d = lane; d < cD; d += 32) p += er[d] * ar[d];
#pragma unroll
        for (int off = 16; off > 0; off >>= 1) p += __shfl_xor_sync(0xffffffffu, p, off);
        if (lane == 0) {
            float sc = p * RSQRTD;
            g_score[r * cNA + a] = sc;
            tw[a] = sc;
        }
    }
    __syncthreads();
    if (tid < cNA) {
        float v = tw[tid];
        float s = fabsf(v);
#pragma unroll
        for (int off = 16; off > 0; off >>= 1) s += __shfl_xor_sync(0xffffffffu, s, off);
        tw[tid] = v / fmaxf(s, EPSV);
    }
    __syncthreads();
    for (int d = tid; d < cD; d += 256) {
        float acc = 0.f;
        for (int a = 0; a < cNA; a++) acc += tw[a] * g_cat_a[((long)(b * cNA + a)) * cCAT + d];
        g_cat_e[(long)r * cCAT + 2 * cD + d] = acc;   // cat_e seg2 (toka)
    }
}

// ---------------- arg_tokenAwared (cat_a seg2) with fused col-L1-norm ----------------
__global__ void argtok_kernel() {
    int a = blockIdx.x, b = blockIdx.y;
    __shared__ float col[cE];
    __shared__ float red[8];
    int tid = threadIdx.x, wid = tid >> 5, lane = tid & 31;
    float v = 0.f;
    if (tid < cE) v = g_score[(b * cE + tid) * cNA + a];
    float s = fabsf(v);
#pragma unroll
    for (int off = 16; off > 0; off >>= 1) s += __shfl_xor_sync(0xffffffffu, s, off);
    if (lane == 0) red[wid] = s;
    __syncthreads();
    if (tid == 0) red[0] = fmaxf(red[0] + red[1], EPSV);
    __syncthreads();
    if (tid < cE) col[tid] = v / red[0];
    __syncthreads();
    for (int d = tid; d < cD; d += 256) {
        float acc = 0.f;
        for (int e = 0; e < cE; e++) acc += col[e] * g_entity2[((long)(b * cE + e)) * cD + d];
        g_cat_a[((long)(b * cNA + a)) * cCAT + 2 * cD + d] = acc;   // cat_a seg2
    }
}

// ------- gathered attention avg: row early-out + column limit (cols >= sls unused) ----
__global__ void __launch_bounds__(128)
t2t_kernel(const float* __restrict__ att0, const float* __restrict__ att1,
           const float* __restrict__ att2) {
    int s = blockIdx.x, b = blockIdx.y;
    int tid = threadIdx.x;  // 128
    int ns = g_nsent[b];
    if (s >= ns) {
        if (tid < cS) g_t2t[((long)b * cS + s) * cS + tid] = 0.f;
        return;
    }
    __shared__ int sj[cS];
    __shared__ float acc[3][cL];
    __shared__ float red0[128], red1[128], red2[128];
    if (tid < cS) sj[tid] = g_idx[b * cS + tid];
    __syncthreads();
    int i = sj[s];
    int lim = g_sls[b];    // gathered columns are sent indices < sls
    float a00 = 0.f, a01 = 0.f, a10 = 0.f, a11 = 0.f, a20 = 0.f, a21 = 0.f;
    if (2 * tid < lim) {
#pragma unroll
        for (int h = 0; h < cH; h++) {
            long rb = (((long)(b * cH + h)) * cL + i) * cL;
            float2 v0 = *(const float2*)(att0 + rb + 2 * tid);
            float2 v1 = *(const float2*)(att1 + rb + 2 * tid);
            float2 v2 = *(const float2*)(att2 + rb + 2 * tid);
            a00 += v0.x; a01 += v0.y;
            a10 += v1.x; a11 += v1.y;
            a20 += v2.x; a21 += v2.y;
        }
    }
    acc[0][2 * tid] = a00; acc[0][2 * tid + 1] = a01;
    acc[1][2 * tid] = a10; acc[1][2 * tid + 1] = a11;
    acc[2][2 * tid] = a20; acc[2][2 * tid + 1] = a21;
    __syncthreads();
    float v0 = 0.f, v1 = 0.f, v2 = 0.f;
    if (tid < ns) {
        int j = sj[tid];
        v0 = acc[0][j]; v1 = acc[1][j]; v2 = acc[2][j];
    }
    red0[tid] = v0; red1[tid] = v1; red2[tid] = v2;
    __syncthreads();
    for (int st = 64; st > 0; st >>= 1) {
        if (tid < st) {
            red0[tid] += red0[tid + st];
            red1[tid] += red1[tid + st];
            red2[tid] += red2[tid + st];
        }
        __syncthreads();
    }
    float r0 = fmaxf(red0[0], EPSV), r1 = fmaxf(red1[0], EPSV), r2 = fmaxf(red2[0], EPSV);
    if (tid < cS)
        g_t2t[((long)b * cS + s) * cS + tid] = (v0 / r0 + v1 / r1 + v2 / r2) * (1.f / 3.f);
}

// ---------------- A_h2h = entmap^T @ a_h2h_tok (cat_e seg1, compacted) ----------------
__global__ void ahh_map_kernel(const float* __restrict__ entmap) {
    int e = blockIdx.x, b = blockIdx.y;
    __shared__ float w[cS];
    __shared__ int act[cS];
    __shared__ int nact_s;
    int tid = threadIdx.x;
    if (tid < cS) {
        bool v = tid < g_nsent[b];
        w[tid] = v ? entmap[((long)b * cS + tid) * cE + e] : 0.f;
    }
    __syncthreads();
    if (tid == 0) {
        int n = 0;
        for (int s = 0; s < cS; s++)
            if (w[s] != 0.f) act[n++] = s;
        nact_s = n;
    }
    __syncthreads();
    int nact = nact_s;
    float acc[3] = {0.f, 0.f, 0.f};
    for (int k = 0; k < nact; k++) {
        int s = act[k];
        float ws = w[s];
        const float* row = g_ahh + ((long)b * cS + s) * cD;
        acc[0] += ws * row[tid];
        acc[1] += ws * row[tid + 256];
        acc[2] += ws * row[tid + 512];
    }
    int r = b * cE + e;
#pragma unroll
    for (int j = 0; j < 3; j++)
        g_cat_e[(long)r * cCAT + cD + j * 256 + tid] = acc[j];   // cat_e seg1
}

// ---------------- a2a = softmax(arg @ arg^T) ----------------
__global__ void a2a_kernel() {
    int a = blockIdx.x, b = blockIdx.y;
    int lane = threadIdx.x;
    float af[24];
    const float* me = g_cat_a + ((long)(b * cNA + a)) * cCAT;
#pragma unroll
    for (int k = 0; k < 24; k++) af[k] = me[lane + 32 * k];
    float myv = 0.f;
    for (int a2 = 0; a2 < cNA; a2++) {
        const float* r = g_cat_a + ((long)(b * cNA + a2)) * cCAT;
        float s = 0.f;
#pragma unroll
        for (int k = 0; k < 24; k++) s += af[k] * r[lane + 32 * k];
#pragma unroll
        for (int off = 16; off > 0; off >>= 1) s += __shfl_xor_sync(0xffffffffu, s, off);
        if (a2 == lane) myv = s;
    }
    float m = myv;
#pragma unroll
    for (int off = 16; off > 0; off >>= 1) m = fmaxf(m, __shfl_xor_sync(0xffffffffu, m, off));
    float p = expf(myv - m);
    float sum = p;
#pragma unroll
    for (int off = 16; off > 0; off >>= 1) sum += __shfl_xor_sync(0xffffffffu, sum, off);
    g_a2a[(b * cNA + a) * cNA + lane] = p / sum;
}

// ---------------- A_u2u = a2a @ arg (cat_a seg1) ----------------
__global__ void au2u_kernel() {
    int a = blockIdx.x, b = blockIdx.y;
    __shared__ float p_s[cNA];
    int tid = threadIdx.x;
    if (tid < cNA) p_s[tid] = g_a2a[(b * cNA + a) * cNA + tid];
    __syncthreads();
    for (int d = tid; d < cD; d += 256) {
        float acc = 0.f;
        for (int a2 = 0; a2 < cNA; a2++)
            acc += p_s[a2] * g_cat_a[((long)(b * cNA + a2)) * cCAT + d];
        g_cat_a[((long)(b * cNA + a)) * cCAT + cD + d] = acc;   // cat_a seg1
    }
}

// ---------------- final: out = gelu(Pe + Pa) @ W2 + b2 ----------------
__device__ __forceinline__ float gelu_exact(float x) {
    return 0.5f * x * (1.f + erff(x * 0.70710678118654752f));
}

__global__ __launch_bounds__(256) void final_kernel(const float* __restrict__ W2,
                                                    const float* __restrict__ b2,
                                                    float* __restrict__ out) {
    int be = blockIdx.x;
    int b = be >> 6;
    __shared__ float pe_s[cNHID];
    __shared__ float w2_s[cNHID];
    int tid = threadIdx.x;
    for (int n = tid; n < cNHID; n += 256) {
        pe_s[n] = g_Pe[(long)be * cNHID + n];
        w2_s[n] = W2[n];
    }
    __syncthreads();
    int w = tid >> 5, lane = tid & 31;
    const float* pa = g_Pa + ((long)(b * cNA + w * 4)) * cNHID;
    float acc0 = 0.f, acc1 = 0.f, acc2 = 0.f, acc3 = 0.f;
    for (int k = 0; k < 32; k++) {
        int n = lane + 32 * k;
        float pe = pe_s[n], w2 = w2_s[n];
        acc0 += gelu_exact(pe + pa[n]) * w2;
        acc1 += gelu_exact(pe + pa[cNHID + n]) * w2;
        acc2 += gelu_exact(pe + pa[2 * cNHID + n]) * w2;
        acc3 += gelu_exact(pe + pa[3 * cNHID + n]) * w2;
    }
#pragma unroll
    for (int off = 16; off > 0; off >>= 1) {
        acc0 += __shfl_xor_sync(0xffffffffu, acc0, off);
        acc1 += __shfl_xor_sync(0xffffffffu, acc1, off);
        acc2 += __shfl_xor_sync(0xffffffffu, acc2, off);
        acc3 += __shfl_xor_sync(0xffffffffu, acc3, off);
    }
    if (lane == 0) {
        float bb = b2[0];
        out[(long)be * cNA + w * 4 + 0] = acc0 + bb;
        out[(long)be * cNA + w * 4 + 1] = acc1 + bb;
        out[(long)be * cNA + w * 4 + 2] = acc2 + bb;
        out[(long)be * cNA + w * 4 + 3] = acc3 + bb;
    }
}

// ---------------- host launcher (multi-stream fork/join, capture-safe) ------------
static cudaStream_t hs1, hs2, hs3;
static cudaEvent_t hevRoot, hevMeta, hevEnt, hevW, hevAhh, hevArg0, hevScore,
                   hevPe01, hevPa;
static bool h_init_done = false;

extern "C" void kernel_launch(void* const* d_in, const int* in_sizes, int n_in,
                              void* d_out, int out_size) {
    const float* emb    = (const float*)d_in[0];
    const float* istr   = (const float*)d_in[1];
    const float* argw   = (const float*)d_in[2];
    const float* entmap = (const float*)d_in[3];
    const float* att0   = (const float*)d_in[4];
    const float* att1   = (const float*)d_in[5];
    const float* att2   = (const float*)d_in[6];
    const float* W_ta   = (const float*)d_in[7];
    const float* b_ta   = (const float*)d_in[8];
    const float* W1     = (const float*)d_in[9];
    const float* b1     = (const float*)d_in[10];
    const float* W2     = (const float*)d_in[11];
    const float* b2     = (const float*)d_in[12];
    const void*  idxs   = d_in[13];
    const void*  blen   = d_in[14];
    float* out = (float*)d_out;

    float *p_entcat, *p_entity2, *p_nonempty, *p_cat_e, *p_cat_a;
    float *p_Pe, *p_Pa, *p_t2t, *p_sent, *p_ahh;
    __nv_bfloat16 *p_WtaH, *p_WtaL, *p_W1eH, *p_W1eL, *p_W1aH, *p_W1aL;
    cudaGetSymbolAddress((void**)&p_entcat, g_entcat);
    cudaGetSymbolAddress((void**)&p_entity2, g_entity2);
    cudaGetSymbolAddress((void**)&p_nonempty, g_nonempty);
    cudaGetSymbolAddress((void**)&p_cat_e, g_cat_e);
    cudaGetSymbolAddress((void**)&p_cat_a, g_cat_a);
    cudaGetSymbolAddress((void**)&p_Pe, g_Pe);
    cudaGetSymbolAddress((void**)&p_Pa, g_Pa);
    cudaGetSymbolAddress((void**)&p_t2t, g_t2t);
    cudaGetSymbolAddress((void**)&p_sent, g_sent_emb);
    cudaGetSymbolAddress((void**)&p_ahh, g_ahh);
    cudaGetSymbolAddress((void**)&p_WtaH, g_WtaT_hi);
    cudaGetSymbolAddress((void**)&p_WtaL, g_WtaT_lo);
    cudaGetSymbolAddress((void**)&p_W1eH, g_W1eT_hi);
    cudaGetSymbolAddress((void**)&p_W1eL, g_W1eT_lo);
    cudaGetSymbolAddress((void**)&p_W1aH, g_W1aT_hi);
    cudaGetSymbolAddress((void**)&p_W1aL, g_W1aT_lo);

    if (!h_init_done) {
        cudaFuncSetAttribute(mma_gemm_kernel,
                             cudaFuncAttributeMaxDynamicSharedMemorySize, GM_SMEM);
        cudaStreamCreateWithFlags(&hs1, cudaStreamNonBlocking);
        cudaStreamCreateWithFlags(&hs2, cudaStreamNonBlocking);
        cudaStreamCreateWithFlags(&hs3, cudaStreamNonBlocking);
        cudaEventCreateWithFlags(&hevRoot, cudaEventDisableTiming);
        cudaEventCreateWithFlags(&hevMeta, cudaEventDisableTiming);
        cudaEventCreateWithFlags(&hevEnt, cudaEventDisableTiming);
        cudaEventCreateWithFlags(&hevW, cudaEventDisableTiming);
        cudaEventCreateWithFlags(&hevAhh, cudaEventDisableTiming);
        cudaEventCreateWithFlags(&hevArg0, cudaEventDisableTiming);
        cudaEventCreateWithFlags(&hevScore, cudaEventDisableTiming);
        cudaEventCreateWithFlags(&hevPe01, cudaEventDisableTiming);
        cudaEventCreateWithFlags(&hevPa, cudaEventDisableTiming);
        meta_kernel<<<1, cB, 0, hs1>>>(idxs, blen);
        meta_kernel<<<1, cB, 0, hs2>>>(idxs, blen);
        meta_kernel<<<1, cB, 0, hs3>>>(idxs, blen);
        cudaStreamSynchronize(hs1);
        cudaStreamSynchronize(hs2);
        cudaStreamSynchronize(hs3);
        h_init_done = true;
    }
    cudaStream_t s1 = hs1, s2 = hs2, s3 = hs3;

    // ---- fork: weight prep on s2 ----
    cudaEventRecord(hevRoot, 0);
    cudaStreamWaitEvent(s2, hevRoot, 0);
    tr_wta_kernel<<<dim3(cCAT / 32, cD / 32), 256, 0, s2>>>(W_ta);
    tr_w1_kernel<<<dim3(cCAT / 32, cNHID / 32, 2), 256, 0, s2>>>(W1);
    cudaEventRecord(hevW, s2);

    // ---- main: meta, entity ----
    meta_kernel<<<1, cB>>>(idxs, blen);
    cudaEventRecord(hevMeta, 0);
    entity_fused_kernel<<<dim3(cE, cB), 256>>>(emb, entmap, istr);
    cudaEventRecord(hevEnt, 0);

    // ---- s1: t2t chain ----
    cudaStreamWaitEvent(s1, hevMeta, 0);
    gather_kernel<<<dim3(cS, cB), 256, 0, s1>>>(emb);
    t2t_kernel<<<dim3(cS, cB), 128, 0, s1>>>(att0, att1, att2);
    gemm_small_kernel<<<dim3((cD + 63) / 64, (cS + 63) / 64, cB), 256, 0, s1>>>(
        p_t2t, p_sent, p_ahh, cS, cD, cS,
        (long)cS * cS, (long)cS * cD, (long)cS * cD);
    ahh_map_kernel<<<dim3(cE, cB), 256, 0, s1>>>(entmap);
    cudaEventRecord(hevAhh, s1);

    // ---- s3: arg chain (cat_a seg0, seg1) ----
    cudaStreamWaitEvent(s3, hevMeta, 0);
    arg_kernel<<<dim3(cNA, cB), 256, 0, s3>>>(emb, argw);
    cudaEventRecord(hevArg0, s3);
    a2a_kernel<<<dim3(cNA, cB), 32, 0, s3>>>();
    au2u_kernel<<<dim3(cNA, cB), 256, 0, s3>>>();

    // ---- main: GEMM1 (entity2, full K) ----
    cudaStreamWaitEvent(0, hevW, 0);
    mma_gemm_kernel<<<dim3(cD / 128, (cB * cE) / 128), 256, GM_SMEM>>>(
        p_entcat, p_WtaH, p_WtaL, p_entity2, cB * cE, cD, cCAT, cCAT, cCAT,
        b_ta, p_nonempty, 0);

    // ---- s2: Pe seg01 (K=1536: entity+ahh) overlapping GEMM1 ----
    cudaStreamWaitEvent(s2, hevEnt, 0);
    cudaStreamWaitEvent(s2, hevAhh, 0);
    mma_gemm_kernel<<<dim3(cNHID / 128, (cB * cE) / 128), 256, GM_SMEM, s2>>>(
        p_cat_e, p_W1eH, p_W1eL, p_Pe, cB * cE, cNHID, 2 * cD, cCAT, cCAT,
        b1, nullptr, 0);
    cudaEventRecord(hevPe01, s2);

    // ---- s3: Pa seg01 (K=1536: arg+au2u) ----
    cudaStreamWaitEvent(s3, hevW, 0);
    mma_gemm_kernel<<<dim3(cNHID / 128, (cB * cNA) / 128), 256, GM_SMEM, s3>>>(
        p_cat_a, p_W1aH, p_W1aL, p_Pa, cB * cNA, cNHID, 2 * cD, cCAT, cCAT,
        nullptr, nullptr, 0);

    // ---- main: fused score+toka ----
    cudaStreamWaitEvent(0, hevArg0, 0);
    score_toka_kernel<<<dim3(cE, cB), 256>>>();
    cudaEventRecord(hevScore, 0);

    // ---- s3: argtok + Pa seg2 (K=768, accum) ----
    cudaStreamWaitEvent(s3, hevScore, 0);
    argtok_kernel<<<dim3(cNA, cB), 256, 0, s3>>>();
    mma_gemm_kernel<<<dim3(cNHID / 128, (cB * cNA) / 128), 256, GM_SMEM, s3>>>(
        p_cat_a + 2 * cD, p_W1aH + 2 * cD, p_W1aL + 2 * cD, p_Pa,
        cB * cNA, cNHID, cD, cCAT, cCAT, nullptr, nullptr, 1);
    cudaEventRecord(hevPa, s3);

    // ---- main: Pe seg2 (K=768, accum) + final ----
    cudaStreamWaitEvent(0, hevPe01, 0);
    mma_gemm_kernel<<<dim3(cNHID / 128, (cB * cE) / 128), 256, GM_SMEM>>>(
        p_cat_e + 2 * cD, p_W1eH + 2 * cD, p_W1eL + 2 * cD, p_Pe,
        cB * cE, cNHID, cD, cCAT, cCAT, nullptr, nullptr, 1);
    cudaStreamWaitEvent(0, hevPa, 0);
    final_kernel<<<cB * cE, 256>>>(W2, b2, out);
}